// round 8
// baseline (speedup 1.0000x reference)
#include <cuda_runtime.h>
#include <cuda_fp16.h>
#include <math.h>
#include <stdint.h>

#define Bn 8
#define Cc 128
#define Aa 16
#define Nn 4096

// log2(e) * (1/sqrt(16)) folded into Q so P = exp2(S)
#define QSCALE 0.3606737602222409f

// Scratch (no allocations allowed)
__device__ __align__(16) __half g_Qh[Bn * Nn * Aa];   // [b][n][16], prescaled
__device__ __align__(16) __half g_Kh[Bn * Nn * Aa];   // [b][n][16]
__device__ __align__(16) __half g_Vh[Bn * Cc * Nn];   // [b][c][n] channel-major

__device__ __forceinline__ uint32_t smem_u32(const void* p) {
    uint32_t a;
    asm("{ .reg .u64 t; cvta.to.shared.u64 t, %1; cvt.u32.u64 %0, t; }"
        : "=r"(a) : "l"(p));
    return a;
}
__device__ __forceinline__ float ex2f(float x) {
    float y; asm("ex2.approx.ftz.f32 %0, %1;" : "=f"(y) : "f"(x)); return y;
}
__device__ __forceinline__ uint32_t packh2(float hi, float lo) {
    uint32_t r;
    asm("cvt.rn.f16x2.f32 %0, %1, %2;" : "=r"(r) : "f"(hi), "f"(lo));
    return r;
}
__device__ __forceinline__ void cp16(uint32_t dst, const void* src) {
    asm volatile("cp.async.cg.shared.global [%0], [%1], 16;"
                 :: "r"(dst), "l"(src) : "memory");
}
#define CP_COMMIT() asm volatile("cp.async.commit_group;" ::: "memory")
#define CP_WAIT_ALL() asm volatile("cp.async.wait_group 0;" ::: "memory")

#define LDSM4(r, addr)                                                        \
    asm volatile("ldmatrix.sync.aligned.m8n8.x4.shared.b16 {%0,%1,%2,%3}, [%4];" \
                 : "=r"((r)[0]), "=r"((r)[1]), "=r"((r)[2]), "=r"((r)[3])     \
                 : "r"(addr))

__device__ __forceinline__ void mma_f16(float* d, const uint32_t* a,
                                        uint32_t b0, uint32_t b1) {
    asm volatile(
        "mma.sync.aligned.m16n8k16.row.col.f32.f16.f16.f32 "
        "{%0,%1,%2,%3}, {%4,%5,%6,%7}, {%8,%9}, {%0,%1,%2,%3};"
        : "+f"(d[0]), "+f"(d[1]), "+f"(d[2]), "+f"(d[3])
        : "r"(a[0]), "r"(a[1]), "r"(a[2]), "r"(a[3]), "r"(b0), "r"(b1));
}

// ---------------------------------------------------------------------------
// Fused QKV projection via fp16 mma.
// C[160 x 128px] = W[160 x 128] * X[128 x 128px] per CTA, then bias (+scale).
// Rows 0-15: Q, 16-31: K, 32-159: V.
// grid (Nn/128, Bn), 256 threads (8 warps, each owns 16 pixels).
// smem: Wh[160][136] fp16 (43520B) + Xh[128][40] fp16 (10240B) + bs[160] f32.
// ---------------------------------------------------------------------------
#define PW_STRIDE 136                       // halves per W row (272B)
#define PX_STRIDE 40                        // halves per X row (80B)
#define SM_WH 0
#define SM_XH 43520
#define SM_BS (43520 + 10240)
#define PROJ_SMEM (SM_BS + 160 * 4)

__global__ __launch_bounds__(256) void proj_qkv_kernel(
    const float* __restrict__ x,
    const float* __restrict__ Wq, const float* __restrict__ bq,
    const float* __restrict__ Wk, const float* __restrict__ bk,
    const float* __restrict__ Wv, const float* __restrict__ bv)
{
    extern __shared__ char smem[];
    __half* Wh = (__half*)(smem + SM_WH);
    __half* Xh = (__half*)(smem + SM_XH);
    float*  bs = (float*)(smem + SM_BS);

    const uint32_t sb = smem_u32(smem);
    const int tid  = threadIdx.x;
    const int wid  = tid >> 5;
    const int lane = tid & 31;
    const int b    = blockIdx.y;
    const int n0g  = blockIdx.x * 128;
    const int nb   = wid * 16;              // warp's pixel base within tile

    // Load W (fp32 -> fp16) and biases into smem
    for (int i = tid; i < 160 * 128; i += 256) {
        int m = i >> 7, c = i & 127;
        float w = (m < 16) ? Wq[m * 128 + c]
                : (m < 32) ? Wk[(m - 16) * 128 + c]
                           : Wv[(m - 32) * 128 + c];
        Wh[m * PW_STRIDE + c] = __float2half_rn(w);
    }
    if (tid < 160)
        bs[tid] = (tid < 16) ? bq[tid] : (tid < 32) ? bk[tid - 16] : bv[tid - 32];

    float acc[10][2][4];
#pragma unroll
    for (int mt = 0; mt < 10; mt++)
#pragma unroll
        for (int nt = 0; nt < 2; nt++)
#pragma unroll
            for (int j = 0; j < 4; j++) acc[mt][nt][j] = 0.f;

    // ldmatrix addresses (validated round-4 patterns)
    // B (X, rows=n cols=k): row = nb + (l&7) + ((l>>4)<<3), coloff = ((l>>3)&1)*16B
    const uint32_t xrow = (uint32_t)(nb + (lane & 7) + ((lane >> 4) << 3));
    const uint32_t xcol = (uint32_t)((lane >> 3) & 1) * 16;
    // A (W, rows=m cols=k): row = mt*16 + (l&7) + ((l>>3)&1)*8, coloff = ((l>>4)&1)*16B
    const uint32_t arow = (uint32_t)((lane & 7) + (((lane >> 3) & 1) << 3));
    const uint32_t acol = (uint32_t)((lane >> 4) & 1) * 16;

    for (int kc = 0; kc < 4; kc++) {
        __syncthreads();
        // x fp32 -> fp16 transposed into Xh[n][k]
#pragma unroll
        for (int j = 0; j < 16; j++) {
            int idx = tid + j * 256;               // 4096
            int kk = idx >> 7, nn = idx & 127;
            Xh[nn * PX_STRIDE + kk] = __float2half_rn(
                x[((size_t)b * Cc + kc * 32 + kk) * Nn + n0g + nn]);
        }
        __syncthreads();

#pragma unroll
        for (int ks = 0; ks < 2; ks++) {
            uint32_t bf[4];
            LDSM4(bf, sb + SM_XH + xrow * (PX_STRIDE * 2) + ks * 32 + xcol);
#pragma unroll
            for (int mt = 0; mt < 10; mt++) {
                uint32_t af[4];
                LDSM4(af, sb + SM_WH + (mt * 16 + arow) * (PW_STRIDE * 2)
                            + (kc * 32 + ks * 16) * 2 + acol);
                mma_f16(acc[mt][0], af, bf[0], bf[1]);
                mma_f16(acc[mt][1], af, bf[2], bf[3]);
            }
        }
    }

    // Epilogue: bias (+QSCALE for Q), store to fp16 scratch
    const int r = lane >> 2;
    const int cb = 2 * (lane & 3);
#pragma unroll
    for (int mt = 0; mt < 10; mt++) {
        int m0 = mt * 16 + r;
#pragma unroll
        for (int nt = 0; nt < 2; nt++) {
            int p = n0g + nb + nt * 8 + cb;
            float v0 = acc[mt][nt][0], v1 = acc[mt][nt][1];
            float v2 = acc[mt][nt][2], v3 = acc[mt][nt][3];
            if (mt == 0) {
                g_Qh[((size_t)b * Nn + p)     * Aa + r]     = __float2half_rn((v0 + bs[m0]) * QSCALE);
                g_Qh[((size_t)b * Nn + p + 1) * Aa + r]     = __float2half_rn((v1 + bs[m0]) * QSCALE);
                g_Qh[((size_t)b * Nn + p)     * Aa + r + 8] = __float2half_rn((v2 + bs[m0 + 8]) * QSCALE);
                g_Qh[((size_t)b * Nn + p + 1) * Aa + r + 8] = __float2half_rn((v3 + bs[m0 + 8]) * QSCALE);
            } else if (mt == 1) {
                g_Kh[((size_t)b * Nn + p)     * Aa + r]     = __float2half_rn(v0 + bs[m0]);
                g_Kh[((size_t)b * Nn + p + 1) * Aa + r]     = __float2half_rn(v1 + bs[m0]);
                g_Kh[((size_t)b * Nn + p)     * Aa + r + 8] = __float2half_rn(v2 + bs[m0 + 8]);
                g_Kh[((size_t)b * Nn + p + 1) * Aa + r + 8] = __float2half_rn(v3 + bs[m0 + 8]);
            } else {
                int c = mt * 16 - 32 + r;
                *(__half2*)&g_Vh[((size_t)b * Cc + c) * Nn + p] =
                    __floats2half2_rn(v0 + bs[m0], v1 + bs[m0]);
                *(__half2*)&g_Vh[((size_t)b * Cc + c + 8) * Nn + p] =
                    __floats2half2_rn(v2 + bs[m0 + 8], v3 + bs[m0 + 8]);
            }
        }
    }
}

// ---------------------------------------------------------------------------
// Flash attention via mma.sync (fp16 in, fp32 accum). Unchanged from R4.
// grid (32, 8), 256 threads (8 warps x 16 query rows = 128 q/CTA).
// ---------------------------------------------------------------------------
#define KT 64
#define NITER (Nn / KT)
#define K_BYTES (64 * 48)               // 3072
#define V_BYTES (128 * 144)             // 18432
#define BUF_BYTES (K_BYTES + V_BYTES)   // 21504
#define STAGE_BYTES (8 * 16 * 133 * 4)  // 68096
#define ATTN_SMEM (STAGE_BYTES > 2 * BUF_BYTES ? STAGE_BYTES : 2 * BUF_BYTES)

__global__ __launch_bounds__(256) void attn_kernel(float* __restrict__ out)
{
    extern __shared__ char smem[];
    const uint32_t sb = smem_u32(smem);
    const int tid  = threadIdx.x;
    const int wid  = tid >> 5;
    const int lane = tid & 31;
    const int lr   = lane & 7, lg = lane >> 3;   // ldmatrix row / group
    const int b    = blockIdx.y;
    const int q0g  = blockIdx.x * 128;

    const __half* Kg = g_Kh + (size_t)b * Nn * Aa;
    const __half* Vg = g_Vh + (size_t)b * Cc * Nn;

    // Q fragment (row-major A, m16n8k16): 16 rows per warp, once
    const char* qp = (const char*)(g_Qh + ((size_t)b * Nn + q0g + wid * 16) * Aa);
    const int qrow = lane >> 2, qcb = (lane & 3) * 4;
    uint32_t qa[4];
    qa[0] = *(const uint32_t*)(qp + qrow * 32 + qcb);
    qa[1] = *(const uint32_t*)(qp + (qrow + 8) * 32 + qcb);
    qa[2] = *(const uint32_t*)(qp + qrow * 32 + qcb + 16);
    qa[3] = *(const uint32_t*)(qp + (qrow + 8) * 32 + qcb + 16);

    float o[16][4];
#pragma unroll
    for (int t = 0; t < 16; t++)
#pragma unroll
        for (int j = 0; j < 4; j++) o[t][j] = 0.f;
    float l0 = 0.f, l1 = 0.f;

    auto fill = [&](int kt, int buf) {
        uint32_t kb = sb + buf * BUF_BYTES;
        uint32_t vb = kb + K_BYTES;
        if (tid < 128) {
            int key = tid >> 1, h = tid & 1;
            cp16(kb + key * 48 + h * 16,
                 (const char*)Kg + ((size_t)(kt * KT + key) * Aa + h * 8) * 2);
        }
#pragma unroll
        for (int i = 0; i < 4; i++) {
            int idx = tid + i * 256;
            int c = idx >> 3, seg = idx & 7;
            cp16(vb + c * 144 + seg * 16,
                 (const char*)Vg + ((size_t)c * Nn + kt * KT + seg * 8) * 2);
        }
        CP_COMMIT();
    };

    fill(0, 0);

    for (int kt = 0; kt < NITER; kt++) {
        CP_WAIT_ALL();
        __syncthreads();
        if (kt + 1 < NITER) fill(kt + 1, (kt + 1) & 1);

        uint32_t kb = sb + (kt & 1) * BUF_BYTES;
        uint32_t vb = kb + K_BYTES;

        float s[8][4];
#pragma unroll
        for (int i = 0; i < 8; i++)
#pragma unroll
            for (int j = 0; j < 4; j++) s[i][j] = 0.f;

#pragma unroll
        for (int nt2 = 0; nt2 < 4; nt2++) {
            uint32_t bk[4];
            uint32_t addr = kb + (uint32_t)(nt2 * 16 + lr + (lg & 2) * 4) * 48
                               + (uint32_t)(lg & 1) * 16;
            LDSM4(bk, addr);
            mma_f16(s[2 * nt2],     qa, bk[0], bk[1]);
            mma_f16(s[2 * nt2 + 1], qa, bk[2], bk[3]);
        }

#pragma unroll
        for (int i = 0; i < 8; i++) {
            s[i][0] = ex2f(s[i][0]);
            s[i][1] = ex2f(s[i][1]);
            s[i][2] = ex2f(s[i][2]);
            s[i][3] = ex2f(s[i][3]);
            l0 += s[i][0] + s[i][1];
            l1 += s[i][2] + s[i][3];
        }

#pragma unroll
        for (int ks = 0; ks < 4; ks++) {
            uint32_t a[4];
            a[0] = packh2(s[2 * ks][1],     s[2 * ks][0]);
            a[1] = packh2(s[2 * ks][3],     s[2 * ks][2]);
            a[2] = packh2(s[2 * ks + 1][1], s[2 * ks + 1][0]);
            a[3] = packh2(s[2 * ks + 1][3], s[2 * ks + 1][2]);
#pragma unroll
            for (int t2 = 0; t2 < 8; t2++) {
                uint32_t bv[4];
                uint32_t addr = vb + (uint32_t)(t2 * 16 + lr + (lg & 2) * 4) * 144
                                   + (uint32_t)(ks * 32) + (uint32_t)(lg & 1) * 16;
                LDSM4(bv, addr);
                mma_f16(o[2 * t2],     a, bv[0], bv[1]);
                mma_f16(o[2 * t2 + 1], a, bv[2], bv[3]);
            }
        }
    }

    l0 += __shfl_xor_sync(0xffffffffu, l0, 1);
    l0 += __shfl_xor_sync(0xffffffffu, l0, 2);
    l1 += __shfl_xor_sync(0xffffffffu, l1, 1);
    l1 += __shfl_xor_sync(0xffffffffu, l1, 2);
    float inv0 = 1.f / l0, inv1 = 1.f / l1;

    __syncthreads();
    float* stage = (float*)smem + wid * (16 * 133);
    const int cb = (lane & 3) * 2;
#pragma unroll
    for (int t = 0; t < 16; t++) {
        stage[qrow * 133 + t * 8 + cb]           = o[t][0] * inv0;
        stage[qrow * 133 + t * 8 + cb + 1]       = o[t][1] * inv0;
        stage[(qrow + 8) * 133 + t * 8 + cb]     = o[t][2] * inv1;
        stage[(qrow + 8) * 133 + t * 8 + cb + 1] = o[t][3] * inv1;
    }
    __syncwarp();

    const int hi = lane >> 4, nloc = lane & 15;
#pragma unroll 8
    for (int it = 0; it < 64; it++) {
        int ch = it * 2 + hi;
        out[((size_t)b * Cc + ch) * Nn + q0g + wid * 16 + nloc] =
            stage[nloc * 133 + ch];
    }
}

// ---------------------------------------------------------------------------
extern "C" void kernel_launch(void* const* d_in, const int* in_sizes, int n_in,
                              void* d_out, int out_size)
{
    const float* x  = (const float*)d_in[0];
    const float* Wq = (const float*)d_in[1];
    const float* bq = (const float*)d_in[2];
    const float* Wk = (const float*)d_in[3];
    const float* bk = (const float*)d_in[4];
    const float* Wv = (const float*)d_in[5];
    const float* bv = (const float*)d_in[6];
    float* out = (float*)d_out;

    cudaFuncSetAttribute(proj_qkv_kernel,
                         cudaFuncAttributeMaxDynamicSharedMemorySize,
                         PROJ_SMEM);
    proj_qkv_kernel<<<dim3(Nn / 128, Bn), 256, PROJ_SMEM>>>(
        x, Wq, bq, Wk, bk, Wv, bv);

    cudaFuncSetAttribute(attn_kernel,
                         cudaFuncAttributeMaxDynamicSharedMemorySize,
                         ATTN_SMEM);
    attn_kernel<<<dim3(Nn / 128, Bn), 256, ATTN_SMEM>>>(out);
}

// round 9
// speedup vs baseline: 1.2251x; 1.2251x over previous
#include <cuda_runtime.h>
#include <cuda_fp16.h>
#include <math.h>
#include <stdint.h>

#define Bn 8
#define Cc 128
#define Aa 16
#define Nn 4096

// log2(e) * (1/sqrt(16)) folded into Q so P = exp2(S)
#define QSCALE 0.3606737602222409f

// Scratch (no allocations allowed)
__device__ __align__(16) __half g_Qh[Bn * Nn * Aa];   // [b][n][16], prescaled
__device__ __align__(16) __half g_Kh[Bn * Nn * Aa];   // [b][n][16]
__device__ __align__(16) __half g_Vh[Bn * Cc * Nn];   // [b][c][n] channel-major

__device__ __forceinline__ uint32_t smem_u32(const void* p) {
    uint32_t a;
    asm("{ .reg .u64 t; cvta.to.shared.u64 t, %1; cvt.u32.u64 %0, t; }"
        : "=r"(a) : "l"(p));
    return a;
}
__device__ __forceinline__ float ex2f(float x) {
    float y; asm("ex2.approx.ftz.f32 %0, %1;" : "=f"(y) : "f"(x)); return y;
}
__device__ __forceinline__ uint32_t packh2(float hi, float lo) {
    uint32_t r;
    asm("cvt.rn.f16x2.f32 %0, %1, %2;" : "=r"(r) : "f"(hi), "f"(lo));
    return r;
}
__device__ __forceinline__ void cp16(uint32_t dst, const void* src) {
    asm volatile("cp.async.cg.shared.global [%0], [%1], 16;"
                 :: "r"(dst), "l"(src) : "memory");
}
#define CP_COMMIT() asm volatile("cp.async.commit_group;" ::: "memory")
#define CP_WAIT_ALL() asm volatile("cp.async.wait_group 0;" ::: "memory")

#define LDSM4(r, addr)                                                        \
    asm volatile("ldmatrix.sync.aligned.m8n8.x4.shared.b16 {%0,%1,%2,%3}, [%4];" \
                 : "=r"((r)[0]), "=r"((r)[1]), "=r"((r)[2]), "=r"((r)[3])     \
                 : "r"(addr))

__device__ __forceinline__ void mma_f16(float* d, const uint32_t* a,
                                        uint32_t b0, uint32_t b1) {
    asm volatile(
        "mma.sync.aligned.m16n8k16.row.col.f32.f16.f16.f32 "
        "{%0,%1,%2,%3}, {%4,%5,%6,%7}, {%8,%9}, {%0,%1,%2,%3};"
        : "+f"(d[0]), "+f"(d[1]), "+f"(d[2]), "+f"(d[3])
        : "r"(a[0]), "r"(a[1]), "r"(a[2]), "r"(a[3]), "r"(b0), "r"(b1));
}

// ---------------------------------------------------------------------------
// Q/K projection -> fp16 [b][n][16]; Q pre-scaled by 0.25*log2(e)  (R4 proven)
// ---------------------------------------------------------------------------
__global__ __launch_bounds__(128) void proj_qk_kernel(
    const float* __restrict__ x,
    const float* __restrict__ Wq, const float* __restrict__ bq,
    const float* __restrict__ Wk, const float* __restrict__ bk)
{
    __shared__ float Wqs[Aa * Cc];
    __shared__ float Wks[Aa * Cc];
    __shared__ float Xs[32][128];

    int b   = blockIdx.y;
    int n0  = blockIdx.x * 128;
    int tid = threadIdx.x;

    for (int i = tid; i < Aa * Cc; i += 128) { Wqs[i] = Wq[i]; Wks[i] = Wk[i]; }

    float qa[Aa], ka[Aa];
#pragma unroll
    for (int a = 0; a < Aa; a++) { qa[a] = 0.f; ka[a] = 0.f; }

    const float* xb = x + (size_t)b * Cc * Nn + n0;

    for (int c0 = 0; c0 < Cc; c0 += 32) {
        __syncthreads();
#pragma unroll
        for (int cc = 0; cc < 32; cc++)
            Xs[cc][tid] = xb[(size_t)(c0 + cc) * Nn + tid];
        __syncthreads();
#pragma unroll 4
        for (int cc = 0; cc < 32; cc++) {
            float xv = Xs[cc][tid];
            int c = c0 + cc;
#pragma unroll
            for (int a = 0; a < Aa; a++) {
                qa[a] += Wqs[a * Cc + c] * xv;
                ka[a] += Wks[a * Cc + c] * xv;
            }
        }
    }

    int n = n0 + tid;
    __half2* qo = (__half2*)(g_Qh + ((size_t)b * Nn + n) * Aa);
    __half2* ko = (__half2*)(g_Kh + ((size_t)b * Nn + n) * Aa);
#pragma unroll
    for (int a2 = 0; a2 < 8; a2++) {
        float q0v = (qa[2 * a2]     + bq[2 * a2])     * QSCALE;
        float q1v = (qa[2 * a2 + 1] + bq[2 * a2 + 1]) * QSCALE;
        qo[a2] = __floats2half2_rn(q0v, q1v);
        ko[a2] = __floats2half2_rn(ka[2 * a2] + bk[2 * a2],
                                   ka[2 * a2 + 1] + bk[2 * a2 + 1]);
    }
}

// ---------------------------------------------------------------------------
// V projection -> fp16 [b][c][n] (channel-major). Tile 32c x 256n, 128 thr.
// (R4 proven)
// ---------------------------------------------------------------------------
__global__ __launch_bounds__(128) void proj_v_kernel(
    const float* __restrict__ x,
    const float* __restrict__ Wv, const float* __restrict__ bv)
{
    __shared__ float Wvs[32][33];
    __shared__ float Xs[32][256];

    int b    = blockIdx.z;
    int c0   = blockIdx.y * 32;
    int n0   = blockIdx.x * 256;
    int tid  = threadIdx.x;
    int lane = tid & 31;
    int wg   = tid >> 5;

    float acc[8][8];
#pragma unroll
    for (int ci = 0; ci < 8; ci++)
#pragma unroll
        for (int j = 0; j < 8; j++) acc[ci][j] = 0.f;

    for (int k0 = 0; k0 < Cc; k0 += 32) {
        __syncthreads();
#pragma unroll
        for (int i = 0; i < 8; i++) {
            int idx = tid + i * 128;
            int kk = idx >> 5, cc = idx & 31;
            Wvs[kk][cc] = Wv[(size_t)(c0 + cc) * Cc + k0 + kk];
        }
#pragma unroll
        for (int i = 0; i < 64; i++) {
            int idx = tid + i * 128;
            int kk = idx >> 8, nn = idx & 255;
            Xs[kk][nn] = x[((size_t)b * Cc + k0 + kk) * Nn + n0 + nn];
        }
        __syncthreads();
#pragma unroll 4
        for (int kk = 0; kk < 32; kk++) {
            float xv[8];
#pragma unroll
            for (int j = 0; j < 8; j++) xv[j] = Xs[kk][lane + j * 32];
#pragma unroll
            for (int ci = 0; ci < 8; ci++) {
                float w = Wvs[kk][wg * 8 + ci];
#pragma unroll
                for (int j = 0; j < 8; j++) acc[ci][j] += w * xv[j];
            }
        }
    }

#pragma unroll
    for (int ci = 0; ci < 8; ci++) {
        int c = c0 + wg * 8 + ci;
        float bias = bv[c];
        __half* vo = g_Vh + ((size_t)b * Cc + c) * Nn + n0;
#pragma unroll
        for (int j = 0; j < 8; j++)
            vo[lane + j * 32] = __float2half_rn(acc[ci][j] + bias);
    }
}

// ---------------------------------------------------------------------------
// Flash attention via mma.sync (fp16 in, fp32 accum).
// NOW: 64 queries/CTA, 4 warps (128 thr), 4 CTAs/SM resident.
// grid (64, 8) = 512 CTAs -> 512/(148*4) = 0.86 of one residency set.
// smem: double-buffered K[64 x 48B] + Vt[128ch x 144B]; epilogue stage.
// ---------------------------------------------------------------------------
#define KT 64
#define NITER (Nn / KT)
#define K_BYTES (64 * 48)               // 3072
#define V_BYTES (128 * 144)             // 18432
#define BUF_BYTES (K_BYTES + V_BYTES)   // 21504
#define STAGE_BYTES (4 * 16 * 133 * 4)  // 34048
#define ATTN_SMEM (STAGE_BYTES > 2 * BUF_BYTES ? STAGE_BYTES : 2 * BUF_BYTES)

__global__ __launch_bounds__(128, 4) void attn_kernel(float* __restrict__ out)
{
    extern __shared__ char smem[];
    const uint32_t sb = smem_u32(smem);
    const int tid  = threadIdx.x;
    const int wid  = tid >> 5;
    const int lane = tid & 31;
    const int lr   = lane & 7, lg = lane >> 3;   // ldmatrix row / group
    const int b    = blockIdx.y;
    const int q0g  = blockIdx.x * 64;

    const __half* Kg = g_Kh + (size_t)b * Nn * Aa;
    const __half* Vg = g_Vh + (size_t)b * Cc * Nn;

    // Q fragment (row-major A, m16n8k16): 16 rows per warp, loaded once
    const char* qp = (const char*)(g_Qh + ((size_t)b * Nn + q0g + wid * 16) * Aa);
    const int qrow = lane >> 2, qcb = (lane & 3) * 4;
    uint32_t qa[4];
    qa[0] = *(const uint32_t*)(qp + qrow * 32 + qcb);
    qa[1] = *(const uint32_t*)(qp + (qrow + 8) * 32 + qcb);
    qa[2] = *(const uint32_t*)(qp + qrow * 32 + qcb + 16);
    qa[3] = *(const uint32_t*)(qp + (qrow + 8) * 32 + qcb + 16);

    float o[16][4];
#pragma unroll
    for (int t = 0; t < 16; t++)
#pragma unroll
        for (int j = 0; j < 4; j++) o[t][j] = 0.f;
    float l0 = 0.f, l1 = 0.f;

    auto fill = [&](int kt, int buf) {
        uint32_t kb = sb + buf * BUF_BYTES;
        uint32_t vb = kb + K_BYTES;
        {   // K: 64 keys x 2 16B chunks = 128 cp (all threads)
            int key = tid >> 1, h = tid & 1;
            cp16(kb + key * 48 + h * 16,
                 (const char*)Kg + ((size_t)(kt * KT + key) * Aa + h * 8) * 2);
        }
#pragma unroll
        for (int i = 0; i < 8; i++) {   // V: 128ch x 8 16B segs = 1024 cp
            int idx = tid + i * 128;
            int c = idx >> 3, seg = idx & 7;
            cp16(vb + c * 144 + seg * 16,
                 (const char*)Vg + ((size_t)c * Nn + kt * KT + seg * 8) * 2);
        }
        CP_COMMIT();
    };

    fill(0, 0);

    for (int kt = 0; kt < NITER; kt++) {
        CP_WAIT_ALL();
        __syncthreads();
        if (kt + 1 < NITER) fill(kt + 1, (kt + 1) & 1);

        uint32_t kb = sb + (kt & 1) * BUF_BYTES;
        uint32_t vb = kb + K_BYTES;

        // S = Q K^T : 8 n-tiles of 8 keys
        float s[8][4];
#pragma unroll
        for (int i = 0; i < 8; i++)
#pragma unroll
            for (int j = 0; j < 4; j++) s[i][j] = 0.f;

#pragma unroll
        for (int nt2 = 0; nt2 < 4; nt2++) {
            uint32_t bk[4];
            uint32_t addr = kb + (uint32_t)(nt2 * 16 + lr + (lg & 2) * 4) * 48
                               + (uint32_t)(lg & 1) * 16;
            LDSM4(bk, addr);
            mma_f16(s[2 * nt2],     qa, bk[0], bk[1]);
            mma_f16(s[2 * nt2 + 1], qa, bk[2], bk[3]);
        }

        // P = exp2(S); accumulate row sums
#pragma unroll
        for (int i = 0; i < 8; i++) {
            s[i][0] = ex2f(s[i][0]);
            s[i][1] = ex2f(s[i][1]);
            s[i][2] = ex2f(s[i][2]);
            s[i][3] = ex2f(s[i][3]);
            l0 += s[i][0] + s[i][1];
            l1 += s[i][2] + s[i][3];
        }

        // O += P V : 4 k-steps x 16 channel tiles
#pragma unroll
        for (int ks = 0; ks < 4; ks++) {
            uint32_t a[4];
            a[0] = packh2(s[2 * ks][1],     s[2 * ks][0]);
            a[1] = packh2(s[2 * ks][3],     s[2 * ks][2]);
            a[2] = packh2(s[2 * ks + 1][1], s[2 * ks + 1][0]);
            a[3] = packh2(s[2 * ks + 1][3], s[2 * ks + 1][2]);
#pragma unroll
            for (int t2 = 0; t2 < 8; t2++) {
                uint32_t bv[4];
                uint32_t addr = vb + (uint32_t)(t2 * 16 + lr + (lg & 2) * 4) * 144
                                   + (uint32_t)(ks * 32) + (uint32_t)(lg & 1) * 16;
                LDSM4(bv, addr);
                mma_f16(o[2 * t2],     a, bv[0], bv[1]);
                mma_f16(o[2 * t2 + 1], a, bv[2], bv[3]);
            }
        }
    }

    // full row sums (lanes sharing a row differ in bits 0..1)
    l0 += __shfl_xor_sync(0xffffffffu, l0, 1);
    l0 += __shfl_xor_sync(0xffffffffu, l0, 2);
    l1 += __shfl_xor_sync(0xffffffffu, l1, 1);
    l1 += __shfl_xor_sync(0xffffffffu, l1, 2);
    float inv0 = 1.f / l0, inv1 = 1.f / l1;

    __syncthreads();   // done with tile buffers; reuse smem as stage
    float* stage = (float*)smem + wid * (16 * 133);
    const int cb = (lane & 3) * 2;
#pragma unroll
    for (int t = 0; t < 16; t++) {
        stage[qrow * 133 + t * 8 + cb]           = o[t][0] * inv0;
        stage[qrow * 133 + t * 8 + cb + 1]       = o[t][1] * inv0;
        stage[(qrow + 8) * 133 + t * 8 + cb]     = o[t][2] * inv1;
        stage[(qrow + 8) * 133 + t * 8 + cb + 1] = o[t][3] * inv1;
    }
    __syncwarp();

    const int hi = lane >> 4, nloc = lane & 15;
#pragma unroll 8
    for (int it = 0; it < 64; it++) {
        int ch = it * 2 + hi;
        out[((size_t)b * Cc + ch) * Nn + q0g + wid * 16 + nloc] =
            stage[nloc * 133 + ch];
    }
}

// ---------------------------------------------------------------------------
extern "C" void kernel_launch(void* const* d_in, const int* in_sizes, int n_in,
                              void* d_out, int out_size)
{
    const float* x  = (const float*)d_in[0];
    const float* Wq = (const float*)d_in[1];
    const float* bq = (const float*)d_in[2];
    const float* Wk = (const float*)d_in[3];
    const float* bk = (const float*)d_in[4];
    const float* Wv = (const float*)d_in[5];
    const float* bv = (const float*)d_in[6];
    float* out = (float*)d_out;

    proj_qk_kernel<<<dim3(Nn / 128, Bn), 128>>>(x, Wq, bq, Wk, bk);
    proj_v_kernel<<<dim3(Nn / 256, Cc / 32, Bn), 128>>>(x, Wv, bv);

    cudaFuncSetAttribute(attn_kernel,
                         cudaFuncAttributeMaxDynamicSharedMemorySize,
                         ATTN_SMEM);
    attn_kernel<<<dim3(Nn / 64, Bn), 128, ATTN_SMEM>>>(out);
}